// round 4
// baseline (speedup 1.0000x reference)
#include <cuda_runtime.h>
#include <math.h>

#define B 2
#define C 256
#define ZS 32
#define HH 48
#define WW 48
#define HW 2304
#define DHW 73728
#define CDHW 18874368
#define TOT 37748736
#define HP 6
#define NPB 73728
#define NTOT 147456

// ---------------- scratch (no allocations allowed) ----------------
__device__ float g_v[TOT];          // v, then mixed s (in-place)
__device__ float g_pe[ZS * C];
__device__ float g_qp[B * ZS * C];  // spatial-max of q, (b,z,c)
__device__ float g_M[B * ZS * ZS];  // depth mixing matrix per batch
__device__ float g_sum[C];
__device__ float g_sumsq[C];
__device__ float g_scale[C];
__device__ float g_shift[C];

__device__ __forceinline__ void atomicMaxFloat(float* addr, float val) {
    int* ia = (int*)addr;
    int old = *ia;
    while (__int_as_float(old) < val) {
        int prev = atomicCAS(ia, old, __float_as_int(val));
        if (prev == old) break;
        old = prev;
    }
}

// ---------------- init: pe table, qp = -inf, stats = 0 ----------------
__global__ void k_init() {
    int i = blockIdx.x * blockDim.x + threadIdx.x;
    if (i < B * ZS * C) g_qp[i] = -3.402823466e38f;
    if (i < ZS * C) {
        int d = i / C, c = i % C;
        int ii = c >> 1;
        // div[i] = exp(2i * (-ln(10000)/C))
        float ang = (float)d * expf(-0.0719557841560637f * (float)ii);
        g_pe[i] = (c & 1) ? cosf(ang) : sinf(ang);
    }
    if (i < C) { g_sum[i] = 0.f; g_sumsq[i] = 0.f; }
}

// ---------------- fused q+v GEMM (x = feat + pe) ----------------
// grid: (18 col-tiles, 4 row-tiles of 512 combined rows, 64 slices)
// rows 0..255 -> v (written to g_v); rows 256..511 -> q (max-reduced into g_qp)
__launch_bounds__(256)
__global__ void k_qv(const float* __restrict__ feat,
                     const float* __restrict__ q_w,
                     const float* __restrict__ v_w) {
    __shared__ float As[16][128];
    __shared__ float Bs[16][128];

    int slice = blockIdx.z;
    int b = slice >> 5, d = slice & 31;
    int colbase = blockIdx.x * 128;
    int rowblock = blockIdx.y;
    bool is_q = rowblock >= 2;
    const float* Wp = is_q ? (q_w + (size_t)(rowblock - 2) * 128 * C)
                           : (v_w + (size_t)rowblock * 128 * C);
    const float* Xp = feat + (size_t)b * CDHW + (size_t)d * HW + colbase;
    const float* pep = g_pe + d * C;

    int tid = threadIdx.x;
    int ty = tid >> 4, tx = tid & 15;
    int wr  = tid >> 1;
    int wk0 = (tid & 1) * 8;
    int xk  = tid >> 4;
    int xj  = (tid & 15) * 8;

    float acc[8][8];
#pragma unroll
    for (int i = 0; i < 8; i++)
#pragma unroll
        for (int j = 0; j < 8; j++) acc[i][j] = 0.f;

    for (int k0 = 0; k0 < C; k0 += 16) {
        float4 w0 = *(const float4*)(Wp + (size_t)wr * C + k0 + wk0);
        float4 w1 = *(const float4*)(Wp + (size_t)wr * C + k0 + wk0 + 4);
        As[wk0 + 0][wr] = w0.x; As[wk0 + 1][wr] = w0.y;
        As[wk0 + 2][wr] = w0.z; As[wk0 + 3][wr] = w0.w;
        As[wk0 + 4][wr] = w1.x; As[wk0 + 5][wr] = w1.y;
        As[wk0 + 6][wr] = w1.z; As[wk0 + 7][wr] = w1.w;

        float pe = pep[k0 + xk];
        const float* xrow = Xp + (size_t)(k0 + xk) * DHW + xj;
        float4 x0 = *(const float4*)(xrow);
        float4 x1 = *(const float4*)(xrow + 4);
        x0.x += pe; x0.y += pe; x0.z += pe; x0.w += pe;
        x1.x += pe; x1.y += pe; x1.z += pe; x1.w += pe;
        *(float4*)&Bs[xk][xj] = x0;
        *(float4*)&Bs[xk][xj + 4] = x1;
        __syncthreads();

#pragma unroll
        for (int kk = 0; kk < 16; kk++) {
            float a[8], bb[8];
            *(float4*)(a)      = *(float4*)&As[kk][ty * 8];
            *(float4*)(a + 4)  = *(float4*)&As[kk][ty * 8 + 4];
            *(float4*)(bb)     = *(float4*)&Bs[kk][tx * 8];
            *(float4*)(bb + 4) = *(float4*)&Bs[kk][tx * 8 + 4];
#pragma unroll
            for (int i = 0; i < 8; i++)
#pragma unroll
                for (int j = 0; j < 8; j++) acc[i][j] += a[i] * bb[j];
        }
        __syncthreads();
    }

    if (!is_q) {
        float* outp = g_v + (size_t)b * CDHW + (size_t)d * HW + colbase;
        int row0 = rowblock * 128 + ty * 8;
#pragma unroll
        for (int i = 0; i < 8; i++) {
            float* o = outp + (size_t)(row0 + i) * DHW + tx * 8;
            *(float4*)(o)     = *(float4*)&acc[i][0];
            *(float4*)(o + 4) = *(float4*)&acc[i][4];
        }
    } else {
        int row0 = (rowblock - 2) * 128 + ty * 8;
#pragma unroll
        for (int i = 0; i < 8; i++) {
            float m = acc[i][0];
#pragma unroll
            for (int j = 1; j < 8; j++) m = fmaxf(m, acc[i][j]);
#pragma unroll
            for (int off = 8; off >= 1; off >>= 1)
                m = fmaxf(m, __shfl_xor_sync(0xffffffffu, m, off));
            if (tx == 0)
                atomicMaxFloat(&g_qp[(size_t)(b * ZS + d) * C + row0 + i], m);
        }
    }
}

// ---------------- offsets / attention / mixing matrix M ----------------
__global__ void k_mrow(const float* __restrict__ offs_w,
                       const float* __restrict__ offs_b,
                       const float* __restrict__ attn_w,
                       const float* __restrict__ attn_b) {
    __shared__ float Ms[64][ZS];
    int t = threadIdx.x;
    if (t >= 64) return;
    int b = t >> 5, z = t & 31;
    const float* qp = g_qp + (size_t)(b * ZS + z) * C;

    float offv[HP], lg[HP];
#pragma unroll
    for (int p = 0; p < HP; p++) { offv[p] = offs_b[p]; lg[p] = attn_b[p]; }
    for (int c = 0; c < C; c++) {
        float q = qp[c];
#pragma unroll
        for (int p = 0; p < HP; p++) {
            offv[p] += q * offs_w[p * C + c];
            lg[p]   += q * attn_w[p * C + c];
        }
    }
    float mx = lg[0];
#pragma unroll
    for (int p = 1; p < HP; p++) mx = fmaxf(mx, lg[p]);
    float s = 0.f;
#pragma unroll
    for (int p = 0; p < HP; p++) { lg[p] = expf(lg[p] - mx); s += lg[p]; }
    float inv = 1.f / s;

    for (int y = 0; y < ZS; y++) Ms[t][y] = 0.f;
#pragma unroll
    for (int p = 0; p < HP; p++) {
        float o = fminf(fmaxf(offv[p], 0.f), (float)(ZS - 1));
        float lo = floorf(o), hi = ceilf(o);
        float fr = o - lo;
        float a = lg[p] * inv;
        Ms[t][(int)lo] += a * (1.f - fr);
        Ms[t][(int)hi] += a * fr;
    }
    for (int y = 0; y < ZS; y++) g_M[t * ZS + y] = Ms[t][y];
}

// ---------------- depth mixing, in place on g_v ----------------
__launch_bounds__(256)
__global__ void k_mix() {
    __shared__ float Ms[ZS * ZS];
    int t = blockIdx.x * 256 + threadIdx.x;   // column id over (b,c,hw)
    int b = (blockIdx.x * 256) / (C * HW);    // uniform per block (C*HW % 256 == 0)
    for (int i = threadIdx.x; i < ZS * ZS; i += 256)
        Ms[i] = g_M[b * ZS * ZS + i];
    __syncthreads();

    int rem = t % (C * HW);
    int c = rem / HW, hw = rem % HW;
    float* base = g_v + (size_t)b * CDHW + (size_t)c * DHW + hw;
    float v[ZS];
#pragma unroll
    for (int y = 0; y < ZS; y++) v[y] = base[(size_t)y * HW];
#pragma unroll
    for (int z = 0; z < ZS; z++) {
        float a = 0.f;
#pragma unroll
        for (int y = 0; y < ZS; y++) a += Ms[z * ZS + y] * v[y];
        base[(size_t)z * HW] = a;
    }
}

// ---------------- output GEMM + fused BN partial stats ----------------
// grid: (1152 col-tiles over N=147456, 2 row-tiles)
__launch_bounds__(256)
__global__ void k_out(const float* __restrict__ o_w, float* __restrict__ out) {
    __shared__ float As[16][128];
    __shared__ float Bs[16][128];

    int n0 = blockIdx.x * 128;
    int b = n0 / NPB;
    int col0 = n0 % NPB;
    const float* Xp = g_v + (size_t)b * CDHW + col0;
    const float* Wp = o_w + (size_t)blockIdx.y * 128 * C;

    int tid = threadIdx.x;
    int ty = tid >> 4, tx = tid & 15;
    int wr  = tid >> 1;
    int wk0 = (tid & 1) * 8;
    int xk  = tid >> 4;
    int xj  = (tid & 15) * 8;

    float acc[8][8];
#pragma unroll
    for (int i = 0; i < 8; i++)
#pragma unroll
        for (int j = 0; j < 8; j++) acc[i][j] = 0.f;

    for (int k0 = 0; k0 < C; k0 += 16) {
        float4 w0 = *(const float4*)(Wp + (size_t)wr * C + k0 + wk0);
        float4 w1 = *(const float4*)(Wp + (size_t)wr * C + k0 + wk0 + 4);
        As[wk0 + 0][wr] = w0.x; As[wk0 + 1][wr] = w0.y;
        As[wk0 + 2][wr] = w0.z; As[wk0 + 3][wr] = w0.w;
        As[wk0 + 4][wr] = w1.x; As[wk0 + 5][wr] = w1.y;
        As[wk0 + 6][wr] = w1.z; As[wk0 + 7][wr] = w1.w;

        const float* xrow = Xp + (size_t)(k0 + xk) * DHW + xj;
        *(float4*)&Bs[xk][xj]     = *(const float4*)(xrow);
        *(float4*)&Bs[xk][xj + 4] = *(const float4*)(xrow + 4);
        __syncthreads();

#pragma unroll
        for (int kk = 0; kk < 16; kk++) {
            float a[8], bb[8];
            *(float4*)(a)      = *(float4*)&As[kk][ty * 8];
            *(float4*)(a + 4)  = *(float4*)&As[kk][ty * 8 + 4];
            *(float4*)(bb)     = *(float4*)&Bs[kk][tx * 8];
            *(float4*)(bb + 4) = *(float4*)&Bs[kk][tx * 8 + 4];
#pragma unroll
            for (int i = 0; i < 8; i++)
#pragma unroll
                for (int j = 0; j < 8; j++) acc[i][j] += a[i] * bb[j];
        }
        __syncthreads();
    }

    float* outp = out + (size_t)b * CDHW + col0;
    int row0 = blockIdx.y * 128 + ty * 8;
#pragma unroll
    for (int i = 0; i < 8; i++) {
        float* o = outp + (size_t)(row0 + i) * DHW + tx * 8;
        *(float4*)(o)     = *(float4*)&acc[i][0];
        *(float4*)(o + 4) = *(float4*)&acc[i][4];
        float s1 = 0.f, s2 = 0.f;
#pragma unroll
        for (int j = 0; j < 8; j++) { s1 += acc[i][j]; s2 += acc[i][j] * acc[i][j]; }
#pragma unroll
        for (int off = 8; off >= 1; off >>= 1) {
            s1 += __shfl_xor_sync(0xffffffffu, s1, off);
            s2 += __shfl_xor_sync(0xffffffffu, s2, off);
        }
        if (tx == 0) {
            atomicAdd(&g_sum[row0 + i], s1);
            atomicAdd(&g_sumsq[row0 + i], s2);
        }
    }
}

// ---------------- finalize BN scale/shift ----------------
__global__ void k_stats(const float* __restrict__ gamma,
                        const float* __restrict__ beta) {
    int o = threadIdx.x;
    if (o >= C) return;
    float cnt = (float)NTOT;
    float mean = g_sum[o] / cnt;
    float var = g_sumsq[o] / cnt - mean * mean;
    float inv = rsqrtf(var + 1e-5f);
    g_scale[o] = inv * gamma[o];
    g_shift[o] = beta[o] - mean * inv * gamma[o];
}

// ---------------- BN apply + residual, in place on out ----------------
__launch_bounds__(256)
__global__ void k_apply(const float* __restrict__ feat, float* __restrict__ out) {
    size_t i = ((size_t)blockIdx.x * 256 + threadIdx.x) * 4;
    if (i >= (size_t)TOT) return;
    int c = (int)((i / DHW) % C);
    float sc = g_scale[c], sh = g_shift[c];
    float4 p = *(float4*)(out + i);
    float4 f = *(const float4*)(feat + i);
    p.x = p.x * sc + sh + f.x;
    p.y = p.y * sc + sh + f.y;
    p.z = p.z * sc + sh + f.z;
    p.w = p.w * sc + sh + f.w;
    *(float4*)(out + i) = p;
}

extern "C" void kernel_launch(void* const* d_in, const int* in_sizes, int n_in,
                              void* d_out, int out_size) {
    const float* feat   = (const float*)d_in[0];
    const float* q_w    = (const float*)d_in[1];
    const float* v_w    = (const float*)d_in[2];
    const float* o_w    = (const float*)d_in[3];
    const float* offs_w = (const float*)d_in[4];
    const float* offs_b = (const float*)d_in[5];
    const float* attn_w = (const float*)d_in[6];
    const float* attn_b = (const float*)d_in[7];
    const float* gamma  = (const float*)d_in[8];
    const float* beta   = (const float*)d_in[9];
    float* out = (float*)d_out;

    k_init<<<64, 256>>>();
    k_qv<<<dim3(18, 4, 64), 256>>>(feat, q_w, v_w);
    k_mrow<<<1, 64>>>(offs_w, offs_b, attn_w, attn_b);
    k_mix<<<4608, 256>>>();
    k_out<<<dim3(1152, 2), 256>>>(o_w, out);
    k_stats<<<1, 256>>>(gamma, beta);
    k_apply<<<36864, 256>>>(feat, out);
}